// round 15
// baseline (speedup 1.0000x reference)
#include <cuda_runtime.h>

#define NB     4
#define IN_DIM 8
#define OUT_D  64
#define N_WIN  64
#define N_SEQ  4096
#define N_REAL 6144
#define PAD    64
#define ROW    (PAD + N_REAL + 8)   // 6216 floats per (b,i) row
#define TT     256                  // t per block
#define OB     16                   // o per block
#define XLEN   320                  // TT + N_WIN

__device__ __align__(16) float g_X[NB][IN_DIM][ROW];

// ---------------- fused zero + scatter: one block per (b,i) row ----------------

__global__ void scatter_kernel(const float* __restrict__ x, const int* __restrict__ idx) {
    const int b = blockIdx.x >> 3;
    const int i = blockIdx.x & 7;
    float* row = g_X[b][i];
    const int tid = threadIdx.x;

    const float4 z = make_float4(0.f, 0.f, 0.f, 0.f);
    for (int j = tid; j < ROW / 4; j += 512)
        reinterpret_cast<float4*>(row)[j] = z;
    __syncthreads();

    const int*   ib = idx + b * N_SEQ;
    const float* xb = x + (size_t)(b * IN_DIM + i) * N_SEQ;
    for (int s = tid; s < N_SEQ; s += 512)
        row[PAD + ib[s]] = xb[s];
}

// ---------------- f32x2 helpers ----------------

__device__ __forceinline__ unsigned long long ffma2(unsigned long long a,
                                                    unsigned long long b,
                                                    unsigned long long c) {
    unsigned long long d;
    asm("fma.rn.f32x2 %0, %1, %2, %3;" : "=l"(d) : "l"(a), "l"(b), "l"(c));
    return d;
}
__device__ __forceinline__ unsigned long long pack2(float v) {
    unsigned long long r;
    unsigned int u = __float_as_uint(v);
    asm("mov.b64 %0, {%1, %1};" : "=l"(r) : "r"(u));
    return r;
}
__device__ __forceinline__ float2 unpack2(unsigned long long v) {
    float2 r;
    asm("mov.b64 {%0, %1}, %2;" : "=f"(r.x), "=f"(r.y) : "l"(v));
    return r;
}
__device__ __forceinline__ unsigned long long lds2(const float* p) {
    return *reinterpret_cast<const unsigned long long*>(p);
}
// odd-lag pair: lo = hi(a), hi = lo(b)
__device__ __forceinline__ unsigned long long comb(unsigned long long a,
                                                   unsigned long long b) {
    unsigned long long r;
    asm("{\n\t.reg .b32 al, ah, bl, bh;\n\t"
        "mov.b64 {al, ah}, %1;\n\t"
        "mov.b64 {bl, bh}, %2;\n\t"
        "mov.b64 %0, {ah, bl};\n\t}"
        : "=l"(r) : "l"(a), "l"(b));
    return r;
}

// ---------------- conv ----------------
// out[b,o,t] = bias[o] + sum_{i,w} W[o,i,w] * Xhat[b,i,t-w]
// Block: one b, 16 o-rows, 256 t. 4 warps × 4 o; lane covers t-pairs
// tl + 64*p, p=0..3. Weights pre-duplicated (w,w) in smem. Single X array;
// odd-lag pairs are formed from consecutive even pairs via the cur/nxt
// software pipeline (zero extra LDS for odd lags).

extern __shared__ float smem[];   // [sW2: 8192 float2 = 64KB][sX: 8*320 floats = 10KB]

__global__ __launch_bounds__(128, 3)
void conv_kernel(const float* __restrict__ weight,
                 const float* __restrict__ bias,
                 float* __restrict__ out) {
    float2* sW2 = reinterpret_cast<float2*>(smem);     // [o][i*64+w] dup pairs
    float*  sX  = smem + 16384;                        // [i][320]

    const int tid    = threadIdx.x;
    const int warp   = tid >> 5;
    const int lane   = tid & 31;
    const int T0     = blockIdx.x * TT;
    const int o_base = blockIdx.y * OB;
    const int b      = blockIdx.z;

    // Weights: 16 rows x 512 floats, duplicated to (v,v) pairs. 2 STS.128 per LDG.128.
    {
        const float4* wg = reinterpret_cast<const float4*>(weight + (size_t)o_base * 512);
        float4* ws = reinterpret_cast<float4*>(sW2);
#pragma unroll
        for (int r = 0; r < 16; ++r) {
            const int f4 = tid + r * 128;
            float4 v = wg[f4];
            ws[f4 * 2 + 0] = make_float4(v.x, v.x, v.y, v.y);
            ws[f4 * 2 + 1] = make_float4(v.z, v.z, v.w, v.w);
        }
    }
    // X tile: sX[i][j] = Xhat[b][i][T0 - 64 + j], 640 float4 total
    {
        float4* xs = reinterpret_cast<float4*>(sX);
#pragma unroll
        for (int k = tid; k < 640; k += 128) {
            const int i = k / 80, j = k % 80;
            xs[i * 80 + j] = *reinterpret_cast<const float4*>(&g_X[b][i][T0] + j * 4);
        }
    }
    __syncthreads();

    const int tl = lane * 2;

    unsigned long long acc[4][4];
#pragma unroll
    for (int oo = 0; oo < 4; ++oo) {
        const unsigned long long bz = pack2(__ldg(&bias[o_base + warp * 4 + oo]));
#pragma unroll
        for (int p = 0; p < 4; ++p) acc[oo][p] = bz;
    }

    const float2* wbase = sW2 + (size_t)(warp * 4) * 512;

#define SUBSTEP(Q, W2)                                                          \
    {                                                                           \
        unsigned long long nxt[4], odd[4];                                      \
        _Pragma("unroll")                                                       \
        for (int p = 0; p < 4; ++p) nxt[p] = lds2(xr + p * 64 - (W2) - 2);      \
        _Pragma("unroll")                                                       \
        for (int oo = 0; oo < 4; ++oo)                                          \
            _Pragma("unroll")                                                   \
            for (int p = 0; p < 4; ++p)                                         \
                acc[oo][p] = ffma2(Q[oo].x, cur[p], acc[oo][p]);                \
        _Pragma("unroll")                                                       \
        for (int p = 0; p < 4; ++p) odd[p] = comb(nxt[p], cur[p]);              \
        _Pragma("unroll")                                                       \
        for (int oo = 0; oo < 4; ++oo)                                          \
            _Pragma("unroll")                                                   \
            for (int p = 0; p < 4; ++p)                                         \
                acc[oo][p] = ffma2(Q[oo].y, odd[p], acc[oo][p]);                \
        _Pragma("unroll")                                                       \
        for (int p = 0; p < 4; ++p) cur[p] = nxt[p];                            \
    }

#pragma unroll 1
    for (int i = 0; i < IN_DIM; ++i) {
        const float*  xr = sX + i * XLEN + tl + 64;   // even pair at [p*64 - w2]
        const float2* wr = wbase + i * 64;
        unsigned long long cur[4];
#pragma unroll
        for (int p = 0; p < 4; ++p) cur[p] = lds2(xr + p * 64);   // E(w2=0)
#pragma unroll
        for (int w4 = 0; w4 < N_WIN; w4 += 4) {
            ulonglong2 qa[4], qb[4];
#pragma unroll
            for (int oo = 0; oo < 4; ++oo) {
                qa[oo] = *reinterpret_cast<const ulonglong2*>(&wr[oo * 512 + w4]);
                qb[oo] = *reinterpret_cast<const ulonglong2*>(&wr[oo * 512 + w4 + 2]);
            }
            SUBSTEP(qa, w4)       // lags w4, w4+1
            SUBSTEP(qb, w4 + 2)   // lags w4+2, w4+3
        }
    }
#undef SUBSTEP

    // Epilogue: bias already in acc; coalesced float2 stores
#pragma unroll
    for (int oo = 0; oo < 4; ++oo) {
        const int o = o_base + warp * 4 + oo;
        float* op = out + ((size_t)(b * OUT_D + o)) * N_REAL + T0 + tl;
#pragma unroll
        for (int p = 0; p < 4; ++p)
            reinterpret_cast<float2*>(op)[p * 32] = unpack2(acc[oo][p]);
    }
}

// ---------------- launch ----------------

extern "C" void kernel_launch(void* const* d_in, const int* in_sizes, int n_in,
                              void* d_out, int out_size) {
    (void)in_sizes; (void)n_in; (void)out_size;
    const float* x      = (const float*)d_in[0];   // (B, IN_DIM, N_SEQ)
    const float* weight = (const float*)d_in[1];   // (OUT_D, IN_DIM, N_WIN)
    const float* bias   = (const float*)d_in[2];   // (OUT_D)
    const int*   idx    = (const int*)  d_in[3];   // (B, N_SEQ)
    float* out = (float*)d_out;                    // (B, OUT_D, N_REAL)

    const size_t shbytes = 8192 * sizeof(float2) + IN_DIM * XLEN * sizeof(float); // 75776
    cudaFuncSetAttribute(conv_kernel, cudaFuncAttributeMaxDynamicSharedMemorySize, (int)shbytes);

    scatter_kernel<<<NB * IN_DIM, 512>>>(x, idx);

    dim3 grid(N_REAL / TT, OUT_D / OB, NB);        // (24, 4, 4) = 384 blocks
    conv_kernel<<<grid, 128, shbytes>>>(weight, bias, out);
}